// round 15
// baseline (speedup 1.0000x reference)
#include <cuda_runtime.h>
#include <cuda_fp16.h>
#include <math.h>
#include <stdint.h>

#define BDIM 1024
#define NB 4
#define NSEQ 1024
#define NHEADS 16
#define HDIM 64
#define ROWS (NB*NSEQ)   // 4096
#define MAXSEQ 1024

// ---------------- scratch (device globals; no allocation allowed) ----------------
__device__ __half g_xn[(size_t)ROWS*BDIM];              // fp16 LN out
__device__ float  g_qkv[(size_t)ROWS*3*BDIM];           // V third used (f32 raw)
__device__ __half g_qkvh[(size_t)ROWS*2*BDIM];          // Q,K fp16
__device__ __half g_vt[(size_t)ROWS*BDIM];              // V^T fp16: [bh*64+d][j]
__device__ __half g_ctx[(size_t)ROWS*BDIM];             // fp16
__device__ float  g_y[(size_t)ROWS*BDIM];
__device__ __half g_mlp[(size_t)ROWS*4*BDIM];
// fp16 TRANSPOSED weights [N, K] K-major
__device__ __half g_qkvw[(size_t)BDIM*3*BDIM];
__device__ __half g_projw[(size_t)BDIM*BDIM];
__device__ __half g_w1[(size_t)BDIM*4*BDIM];
__device__ __half g_w2[(size_t)4*BDIM*BDIM];

// ---------------- helpers ----------------
__device__ __forceinline__ void mma_f16(float c[4], const uint32_t a[4], const uint32_t b[2]) {
    asm volatile(
        "mma.sync.aligned.m16n8k16.row.col.f32.f16.f16.f32 "
        "{%0,%1,%2,%3}, {%4,%5,%6,%7}, {%8,%9}, {%0,%1,%2,%3};"
        : "+f"(c[0]), "+f"(c[1]), "+f"(c[2]), "+f"(c[3])
        : "r"(a[0]), "r"(a[1]), "r"(a[2]), "r"(a[3]), "r"(b[0]), "r"(b[1]));
}

__device__ __forceinline__ void ldsm_x4(uint32_t& r0, uint32_t& r1, uint32_t& r2, uint32_t& r3,
                                        uint32_t addr) {
    asm volatile("ldmatrix.sync.aligned.m8n8.x4.shared.b16 {%0,%1,%2,%3}, [%4];"
                 : "=r"(r0), "=r"(r1), "=r"(r2), "=r"(r3) : "r"(addr));
}

__device__ __forceinline__ void cp_async16(uint32_t smem_addr, const void* gptr) {
    asm volatile("cp.async.cg.shared.global [%0], [%1], 16;"
                 :: "r"(smem_addr), "l"(gptr));
}
__device__ __forceinline__ void cp_commit() { asm volatile("cp.async.commit_group;"); }
template<int N>
__device__ __forceinline__ void cp_wait() { asm volatile("cp.async.wait_group %0;" :: "n"(N)); }

__device__ __forceinline__ uint32_t h2u(__half2 h) { return *reinterpret_cast<uint32_t*>(&h); }

// ---------------- merged weight transpose + fp16 round (single launch) ----------------
__global__ __launch_bounds__(256) void transpose_all_kernel(
    const float* __restrict__ qkv_w, __half* __restrict__ qkvw,
    const float* __restrict__ proj_w, __half* __restrict__ projw,
    const float* __restrict__ w1, __half* __restrict__ w1t,
    const float* __restrict__ w2, __half* __restrict__ w2t)
{
    __shared__ float t[32][33];
    const int bid = blockIdx.x;
    const float* in; __half* out; int K, N, bx, by;
    if (bid < 3072)      { in = qkv_w;  out = qkvw;  K = 1024; N = 3072; bx = bid % 96;  by = bid / 96; }
    else if (bid < 4096) { int q = bid - 3072; in = proj_w; out = projw; K = 1024; N = 1024; bx = q % 32;  by = q / 32; }
    else if (bid < 8192) { int q = bid - 4096; in = w1;     out = w1t;   K = 1024; N = 4096; bx = q % 128; by = q / 128; }
    else                 { int q = bid - 8192; in = w2;     out = w2t;   K = 4096; N = 1024; bx = q % 32;  by = q / 32; }
    const int n0 = bx * 32, k0 = by * 32;
    const int tx = threadIdx.x & 31, ty = threadIdx.x >> 5;
    #pragma unroll
    for (int i = 0; i < 32; i += 8)
        t[ty + i][tx] = in[(size_t)(k0 + ty + i) * N + n0 + tx];
    __syncthreads();
    #pragma unroll
    for (int i = 0; i < 32; i += 8)
        out[(size_t)(n0 + ty + i) * K + k0 + tx] = __float2half_rn(t[tx][ty + i]);
}

// ---------------- V transpose: f32 [token][2048+h*64+d] -> fp16 [bh*64+d][j] ----------------
__global__ __launch_bounds__(256) void transpose_v_kernel(
    const float* __restrict__ qkvf, __half* __restrict__ vt)
{
    __shared__ float t[32][33];
    const int bh = blockIdx.z;
    const int b = bh >> 4, h = bh & 15;
    const int j0 = blockIdx.x * 32, d0 = blockIdx.y * 32;
    const int tx = threadIdx.x & 31, ty = threadIdx.x >> 5;
    #pragma unroll
    for (int i = 0; i < 32; i += 8)
        t[ty + i][tx] = qkvf[(size_t)(b * NSEQ + j0 + ty + i) * (3 * BDIM) + 2 * BDIM + h * HDIM + d0 + tx];
    __syncthreads();
    #pragma unroll
    for (int i = 0; i < 32; i += 8)
        vt[(size_t)(bh * HDIM + d0 + ty + i) * NSEQ + j0 + tx] = __float2half_rn(t[tx][ty + i]);
}

// ---------------- LayerNorm: warp per row; fp16 output ----------------
__global__ __launch_bounds__(256) void ln_kernel(const float* __restrict__ x,
    const float* __restrict__ g, const float* __restrict__ b, __half* __restrict__ out)
{
    const int row  = blockIdx.x * 8 + (threadIdx.x >> 5);
    const int lane = threadIdx.x & 31;
    const float4* xr = reinterpret_cast<const float4*>(x + (size_t)row * BDIM);
    float4 v[8];
    float s = 0.0f;
    #pragma unroll
    for (int i = 0; i < 8; i++) {
        v[i] = xr[lane + 32 * i];
        s += v[i].x + v[i].y + v[i].z + v[i].w;
    }
    #pragma unroll
    for (int o = 16; o > 0; o >>= 1) s += __shfl_xor_sync(0xffffffffu, s, o);
    const float mu = s * (1.0f / BDIM);
    float q = 0.0f;
    #pragma unroll
    for (int i = 0; i < 8; i++) {
        v[i].x -= mu; v[i].y -= mu; v[i].z -= mu; v[i].w -= mu;
        q += v[i].x*v[i].x + v[i].y*v[i].y + v[i].z*v[i].z + v[i].w*v[i].w;
    }
    #pragma unroll
    for (int o = 16; o > 0; o >>= 1) q += __shfl_xor_sync(0xffffffffu, q, o);
    const float rinv = rsqrtf(q * (1.0f / BDIM) + 1e-5f);
    __half* orow = out + (size_t)row * BDIM;
    #pragma unroll
    for (int i = 0; i < 8; i++) {
        float4 gg = reinterpret_cast<const float4*>(g)[lane + 32 * i];
        float4 bb = reinterpret_cast<const float4*>(b)[lane + 32 * i];
        __half2 h01 = __floats2half2_rn(v[i].x * rinv * gg.x + bb.x,
                                        v[i].y * rinv * gg.y + bb.y);
        __half2 h23 = __floats2half2_rn(v[i].z * rinv * gg.z + bb.z,
                                        v[i].w * rinv * gg.w + bb.w);
        uint2 u = { h2u(h01), h2u(h23) };
        *reinterpret_cast<uint2*>(orow + (lane + 32 * i) * 4) = u;
    }
}

// ---------------- 3-stage cp.async FP16 GEMM with ldmatrix: 128 threads, warp 64x64 ----------------
// Padded 144B rows (stride/16 odd -> ldmatrix conflict-free); standard mma fragment maps.
enum { EPI_BIAS = 0, EPI_GELU = 1, EPI_RESGATE = 2 };

#define ROWB 144
#define ASTG (128*ROWB)                // 18432 per operand per stage
#define FSTAGE_B (2*ASTG)              // 36864
#define GEMM_SMEM (3*FSTAGE_B)         // 110592 bytes

template<int EPI>
__global__ __launch_bounds__(128) void h16gemm_kernel(
    const __half* __restrict__ A, const __half* __restrict__ Wt,
    const float* __restrict__ bias, const float* __restrict__ res,
    const float* __restrict__ gate, void* __restrict__ Cv, void* __restrict__ Cv2,
    int M, int N, int K)
{
    constexpr int BK = 64;
    extern __shared__ uint32_t sm[];
    const uint32_t sm_u = (uint32_t)__cvta_generic_to_shared(sm);

    const int tid  = threadIdx.x;
    const int lane = tid & 31;
    const int wid  = tid >> 5;
    const int g    = lane >> 2;
    const int t4   = lane & 3;
    const int mWarp = (wid >> 1) * 64;
    const int nWarp = (wid & 1) * 64;

    // ldmatrix per-lane offset: quad q rows/halves mapping
    const int lq = lane >> 3, lr8 = lane & 7;
    const uint32_t laneoff = (uint32_t)(((lq & 1) * 8 + lr8) * ROWB + (lq >> 1) * 16);

    // global->smem loaders
    const int lrow   = tid >> 3;
    const int lchunk = tid & 7;
    const __half* Ap = A  + (size_t)(blockIdx.y * 128 + lrow) * K + lchunk * 8;
    const __half* Bp = Wt + (size_t)(blockIdx.x * 128 + lrow) * K + lchunk * 8;

    const int nT = K / BK;

    #pragma unroll
    for (int t = 0; t < 2; t++) {
        const uint32_t ab = sm_u + t * FSTAGE_B;
        #pragma unroll
        for (int p = 0; p < 8; p++) {
            cp_async16(ab + (uint32_t)((lrow + p * 16) * ROWB + lchunk * 16),
                       Ap + (size_t)t * BK + (size_t)(p * 16) * K);
            cp_async16(ab + (uint32_t)(ASTG + (lrow + p * 16) * ROWB + lchunk * 16),
                       Bp + (size_t)t * BK + (size_t)(p * 16) * K);
        }
        cp_commit();
    }

    float acc[4][8][4] = {};
    int stage = 0;

    for (int t = 0; t < nT; t++) {
        cp_wait<1>();
        __syncthreads();

        const int tn = t + 2;
        if (tn < nT) {
            int sl = stage + 2; if (sl >= 3) sl -= 3;
            const uint32_t ab = sm_u + sl * FSTAGE_B;
            #pragma unroll
            for (int p = 0; p < 8; p++) {
                cp_async16(ab + (uint32_t)((lrow + p * 16) * ROWB + lchunk * 16),
                           Ap + (size_t)tn * BK + (size_t)(p * 16) * K);
                cp_async16(ab + (uint32_t)(ASTG + (lrow + p * 16) * ROWB + lchunk * 16),
                           Bp + (size_t)tn * BK + (size_t)(p * 16) * K);
            }
        }
        cp_commit();

        const uint32_t aR = sm_u + stage * FSTAGE_B + (uint32_t)(mWarp * ROWB) + laneoff;
        const uint32_t bR = sm_u + stage * FSTAGE_B + ASTG + (uint32_t)(nWarp * ROWB) + laneoff;
        #pragma unroll
        for (int kc = 0; kc < 4; kc++) {
            uint32_t bf[8][2];
            #pragma unroll
            for (int ntp = 0; ntp < 4; ntp++) {
                uint32_t r0, r1, r2, r3;
                ldsm_x4(r0, r1, r2, r3, bR + (uint32_t)(ntp * 16 * ROWB + kc * 32));
                bf[2*ntp][0] = r0; bf[2*ntp][1] = r2;
                bf[2*ntp+1][0] = r1; bf[2*ntp+1][1] = r3;
            }
            #pragma unroll
            for (int mi = 0; mi < 4; mi++) {
                uint32_t a0, a1, a2, a3;
                ldsm_x4(a0, a1, a2, a3, aR + (uint32_t)(mi * 16 * ROWB + kc * 32));
                uint32_t af[4] = { a0, a1, a2, a3 };
                #pragma unroll
                for (int ni = 0; ni < 8; ni++)
                    mma_f16(acc[mi][ni], af, bf[ni]);
            }
        }
        stage = (stage + 1 == 3) ? 0 : stage + 1;
    }

    // epilogue (standard c-frag)
    const float gt = (EPI == EPI_RESGATE) ? gate[0] : 0.0f;
    #pragma unroll
    for (int mi = 0; mi < 4; mi++) {
        const int row0 = blockIdx.y * 128 + mWarp + mi * 16 + g;
        #pragma unroll
        for (int ni = 0; ni < 8; ni++) {
            const int col = blockIdx.x * 128 + nWarp + ni * 8 + t4 * 2;
            const float b0 = bias[col], b1 = bias[col + 1];
            #pragma unroll
            for (int h = 0; h < 2; h++) {
                const int row = row0 + h * 8;
                float v0 = acc[mi][ni][2 * h + 0] + b0;
                float v1 = acc[mi][ni][2 * h + 1] + b1;
                if (EPI == EPI_BIAS) {
                    if (col < 2 * BDIM) {
                        *reinterpret_cast<uint32_t*>((__half*)Cv2 + (size_t)row * (2 * BDIM) + col) =
                            h2u(__floats2half2_rn(v0, v1));
                    } else {
                        float* C = (float*)Cv;
                        *reinterpret_cast<float2*>(C + (size_t)row * N + col) = make_float2(v0, v1);
                    }
                }
                if (EPI == EPI_GELU) {
                    v0 = 0.5f * v0 * (1.0f + erff(v0 * 0.70710678118654752f));
                    v1 = 0.5f * v1 * (1.0f + erff(v1 * 0.70710678118654752f));
                    *reinterpret_cast<uint32_t*>((__half*)Cv + (size_t)row * N + col) =
                        h2u(__floats2half2_rn(v0, v1));
                }
                if (EPI == EPI_RESGATE) {
                    float* C = (float*)Cv;
                    const size_t off = (size_t)row * N + col;
                    *reinterpret_cast<float2*>(C + off) =
                        make_float2(res[off] + gt * v0, res[off + 1] + gt * v1);
                }
            }
        }
    }
}

// ---------------- Fused flash attention: fp16 + ldmatrix, padded 144B strides ----------------
#define K_BYTES (64*ROWB)              // 9216
#define VT_BYTES (64*ROWB)             // 9216
#define SLOT_B  (K_BYTES+VT_BYTES)     // 18432
#define MK_B    (2*SLOT_B)             // 36864
#define REL_B   (MK_B + 512)           // 37376
#define FL_SMEM (REL_B + 8192)         // 45568 bytes

__global__ __launch_bounds__(256, 2) void flash_attn_kernel(
    const __half* __restrict__ qkvh, const __half* __restrict__ vt,
    const int* __restrict__ mask, const float* __restrict__ rel,
    __half* __restrict__ ctx)
{
    constexpr float SCALE = 0.125f;
    constexpr float L2E = 1.4426950408889634f;

    extern __shared__ __align__(16) char smc[];
    const uint32_t sm_u = (uint32_t)__cvta_generic_to_shared(smc);
    const int* mki  = reinterpret_cast<const int*>(smc + MK_B);
    float* rel_s    = reinterpret_cast<float*>(smc + REL_B);

    const int bh = blockIdx.y;
    const int b = bh >> 4, h = bh & 15;
    const int i0 = blockIdx.x * 128;
    const int tid = threadIdx.x, lane = tid & 31, w = tid >> 5;
    const int g = lane >> 2, t4 = lane & 3;

    const int lq = lane >> 3, lr8 = lane & 7;
    const uint32_t laneoff = (uint32_t)(((lq & 1) * 8 + lr8) * ROWB + (lq >> 1) * 16);

    // loaders: K rows (tokens) / Vt rows (d)
    const int ldr = tid >> 2;
    const int kc  = tid & 3;
    const __half* khbase = qkvh + (size_t)(b * NSEQ + ldr) * (2 * BDIM) + BDIM + h * HDIM + kc * 16;
    const __half* vtbase = vt + (size_t)(bh * HDIM + ldr) * NSEQ + kc * 16;

    // prologue: tile 0 -> slot 0
    {
        const uint32_t kdst = sm_u + (uint32_t)(ldr * ROWB + kc * 32);
        cp_async16(kdst, khbase);
        cp_async16(kdst + 16, khbase + 8);
        const uint32_t vdst = sm_u + (uint32_t)(K_BYTES + ldr * ROWB + kc * 32);
        cp_async16(vdst, vtbase);
        cp_async16(vdst + 16, vtbase + 8);
        if (tid < 16)
            cp_async16(sm_u + (uint32_t)(MK_B + tid * 16), mask + b * NSEQ + tid * 4);
        cp_commit();
    }

    for (int idx = tid; idx < 2 * MAXSEQ - 1; idx += 256)
        rel_s[idx] = rel[(size_t)idx * NHEADS + h];

    const int irow0 = i0 + w * 16 + g;
    const int irow1 = irow0 + 8;

    // Q a-fragments from gmem, STANDARD layout: a0=(row g, k=2t4,2t4+1) etc.
    uint32_t Qa[4][4];
    {
        const char* q0b = (const char*)(qkvh + (size_t)(b * NSEQ + irow0) * (2 * BDIM) + h * HDIM);
        const char* q1b = (const char*)(qkvh + (size_t)(b * NSEQ + irow1) * (2 * BDIM) + h * HDIM);
        #pragma unroll
        for (int kt = 0; kt < 4; kt++) {
            Qa[kt][0] = *reinterpret_cast<const uint32_t*>(q0b + kt * 32 + 4 * t4);
            Qa[kt][1] = *reinterpret_cast<const uint32_t*>(q1b + kt * 32 + 4 * t4);
            Qa[kt][2] = *reinterpret_cast<const uint32_t*>(q0b + kt * 32 + 16 + 4 * t4);
            Qa[kt][3] = *reinterpret_cast<const uint32_t*>(q1b + kt * 32 + 16 + 4 * t4);
        }
    }

    const int mi0 = mask[b * NSEQ + irow0];
    const int mi1 = mask[b * NSEQ + irow1];

    float m0 = -INFINITY, m1 = -INFINITY, l0 = 0.0f, l1 = 0.0f;
    float Oc[8][4] = {};

    for (int jt = 0; jt < NSEQ / 64; jt++) {
        cp_wait<0>();
        __syncthreads();

        if (jt + 1 < NSEQ / 64) {
            const int ns = (jt + 1) & 1;
            const __half* kp = khbase + (size_t)(jt + 1) * 64 * (2 * BDIM);
            const __half* vp = vtbase + (size_t)(jt + 1) * 64;
            const uint32_t kdst = sm_u + (uint32_t)(ns * SLOT_B + ldr * ROWB + kc * 32);
            cp_async16(kdst, kp);
            cp_async16(kdst + 16, kp + 8);
            const uint32_t vdst = sm_u + (uint32_t)(ns * SLOT_B + K_BYTES + ldr * ROWB + kc * 32);
            cp_async16(vdst, vp);
            cp_async16(vdst + 16, vp + 8);
            if (tid < 16)
                cp_async16(sm_u + (uint32_t)(MK_B + ns * 256 + tid * 16),
                           mask + b * NSEQ + (jt + 1) * 64 + tid * 4);
            cp_commit();
        }

        const int slot = jt & 1;
        const uint32_t kR = sm_u + (uint32_t)(slot * SLOT_B) + laneoff;
        const uint32_t vR = kR + K_BYTES;
        const int* mkp = mki + slot * 64;

        // S = Q @ K^T  (fp16; K b-frags via ldmatrix)
        float S[8][4] = {};
        #pragma unroll
        for (int kt = 0; kt < 4; kt++) {
            uint32_t kb[8][2];
            #pragma unroll
            for (int ntp = 0; ntp < 4; ntp++) {
                uint32_t r0, r1, r2, r3;
                ldsm_x4(r0, r1, r2, r3, kR + (uint32_t)(ntp * 16 * ROWB + kt * 32));
                kb[2*ntp][0] = r0; kb[2*ntp][1] = r2;
                kb[2*ntp+1][0] = r1; kb[2*ntp+1][1] = r3;
            }
            #pragma unroll
            for (int nt = 0; nt < 8; nt++)
                mma_f16(S[nt], Qa[kt], kb[nt]);
        }

        // scale + rel bias + mask; row max
        float tmax0 = -INFINITY, tmax1 = -INFINITY;
        #pragma unroll
        for (int nt = 0; nt < 8; nt++) {
            const int j0 = jt * 64 + nt * 8 + 2 * t4;
            const int mk0 = mkp[nt * 8 + 2 * t4];
            const int mk1 = mkp[nt * 8 + 2 * t4 + 1];
            float s0 = S[nt][0] * SCALE + rel_s[irow0 - j0 + (MAXSEQ - 1)];
            float s1 = S[nt][1] * SCALE + rel_s[irow0 - j0 - 1 + (MAXSEQ - 1)];
            float s2 = S[nt][2] * SCALE + rel_s[irow1 - j0 + (MAXSEQ - 1)];
            float s3 = S[nt][3] * SCALE + rel_s[irow1 - j0 - 1 + (MAXSEQ - 1)];
            if (mi0 == 0 || mk0 == 0) s0 = -1e9f;
            if (mi0 == 0 || mk1 == 0) s1 = -1e9f;
            if (mi1 == 0 || mk0 == 0) s2 = -1e9f;
            if (mi1 == 0 || mk1 == 0) s3 = -1e9f;
            S[nt][0] = s0; S[nt][1] = s1; S[nt][2] = s2; S[nt][3] = s3;
            tmax0 = fmaxf(tmax0, fmaxf(s0, s1));
            tmax1 = fmaxf(tmax1, fmaxf(s2, s3));
        }
        tmax0 = fmaxf(tmax0, __shfl_xor_sync(0xffffffffu, tmax0, 1));
        tmax0 = fmaxf(tmax0, __shfl_xor_sync(0xffffffffu, tmax0, 2));
        tmax1 = fmaxf(tmax1, __shfl_xor_sync(0xffffffffu, tmax1, 1));
        tmax1 = fmaxf(tmax1, __shfl_xor_sync(0xffffffffu, tmax1, 2));

        const float mn0 = fmaxf(m0, tmax0);
        const float mn1 = fmaxf(m1, tmax1);
        const float sc0 = exp2f((m0 - mn0) * L2E);
        const float sc1 = exp2f((m1 - mn1) * L2E);
        m0 = mn0; m1 = mn1;

        float ts0 = 0.0f, ts1 = 0.0f;
        #pragma unroll
        for (int nt = 0; nt < 8; nt++) {
            S[nt][0] = exp2f((S[nt][0] - mn0) * L2E);
            S[nt][1] = exp2f((S[nt][1] - mn0) * L2E);
            S[nt][2] = exp2f((S[nt][2] - mn1) * L2E);
            S[nt][3] = exp2f((S[nt][3] - mn1) * L2E);
            ts0 += S[nt][0] + S[nt][1];
            ts1 += S[nt][2] + S[nt][3];
        }
        ts0 += __shfl_xor_sync(0xffffffffu, ts0, 1);
        ts0 += __shfl_xor_sync(0xffffffffu, ts0, 2);
        ts1 += __shfl_xor_sync(0xffffffffu, ts1, 1);
        ts1 += __shfl_xor_sync(0xffffffffu, ts1, 2);
        l0 = l0 * sc0 + ts0;
        l1 = l1 * sc1 + ts1;

        #pragma unroll
        for (int nt = 0; nt < 8; nt++) {
            Oc[nt][0] *= sc0; Oc[nt][1] *= sc0;
            Oc[nt][2] *= sc1; Oc[nt][3] *= sc1;
        }

        // O += P @ V : a-frag = packed S regs (standard), b-frag = V^T via ldmatrix
        #pragma unroll
        for (int kcc = 0; kcc < 4; kcc++) {
            const int nt0 = 2 * kcc, nt1 = nt0 + 1;
            uint32_t af[4];
            af[0] = h2u(__floats2half2_rn(S[nt0][0], S[nt0][1]));
            af[1] = h2u(__floats2half2_rn(S[nt0][2], S[nt0][3]));
            af[2] = h2u(__floats2half2_rn(S[nt1][0], S[nt1][1]));
            af[3] = h2u(__floats2half2_rn(S[nt1][2], S[nt1][3]));
            uint32_t vb[8][2];
            #pragma unroll
            for (int ntp = 0; ntp < 4; ntp++) {
                uint32_t r0, r1, r2, r3;
                ldsm_x4(r0, r1, r2, r3, vR + (uint32_t)(ntp * 16 * ROWB + kcc * 32));
                vb[2*ntp][0] = r0; vb[2*ntp][1] = r2;
                vb[2*ntp+1][0] = r1; vb[2*ntp+1][1] = r3;
            }
            #pragma unroll
            for (int nt = 0; nt < 8; nt++)
                mma_f16(Oc[nt], af, vb[nt]);
        }
    }

    // writeback ctx = O / l -> fp16
    const float inv0 = 1.0f / l0;
    const float inv1 = 1.0f / l1;
    #pragma unroll
    for (int nt = 0; nt < 8; nt++) {
        const int col = h * HDIM + nt * 8 + 2 * t4;
        *reinterpret_cast<uint32_t*>(ctx + (size_t)(b * NSEQ + irow0) * BDIM + col) =
            h2u(__floats2half2_rn(Oc[nt][0] * inv0, Oc[nt][1] * inv0));
        *reinterpret_cast<uint32_t*>(ctx + (size_t)(b * NSEQ + irow1) * BDIM + col) =
            h2u(__floats2half2_rn(Oc[nt][2] * inv1, Oc[nt][3] * inv1));
    }
}

// ---------------- launch ----------------
extern "C" void kernel_launch(void* const* d_in, const int* in_sizes, int n_in,
                              void* d_out, int out_size)
{
    const float* x      = (const float*)d_in[0];
    const int*   mask   = (const int*)  d_in[1];
    const float* ln1_g  = (const float*)d_in[2];
    const float* ln1_b  = (const float*)d_in[3];
    const float* qkv_w  = (const float*)d_in[4];
    const float* qkv_b  = (const float*)d_in[5];
    const float* proj_w = (const float*)d_in[6];
    const float* proj_b = (const float*)d_in[7];
    const float* rel    = (const float*)d_in[8];
    const float* ln2_g  = (const float*)d_in[9];
    const float* ln2_b  = (const float*)d_in[10];
    const float* w1     = (const float*)d_in[11];
    const float* b1     = (const float*)d_in[12];
    const float* w2     = (const float*)d_in[13];
    const float* b2     = (const float*)d_in[14];
    const float* gate1  = (const float*)d_in[15];
    const float* gate2  = (const float*)d_in[16];
    float* out = (float*)d_out;

    __half *xn, *ctx, *mlp, *qkvw, *projw, *w1t, *w2t, *qkvh, *vt;
    float *qkv, *y;
    cudaGetSymbolAddress((void**)&xn,    g_xn);
    cudaGetSymbolAddress((void**)&qkv,   g_qkv);
    cudaGetSymbolAddress((void**)&qkvh,  g_qkvh);
    cudaGetSymbolAddress((void**)&vt,    g_vt);
    cudaGetSymbolAddress((void**)&ctx,   g_ctx);
    cudaGetSymbolAddress((void**)&y,     g_y);
    cudaGetSymbolAddress((void**)&mlp,   g_mlp);
    cudaGetSymbolAddress((void**)&qkvw,  g_qkvw);
    cudaGetSymbolAddress((void**)&projw, g_projw);
    cudaGetSymbolAddress((void**)&w1t,   g_w1);
    cudaGetSymbolAddress((void**)&w2t,   g_w2);

    static bool attr_set = false;
    if (!attr_set) {
        cudaFuncSetAttribute(h16gemm_kernel<EPI_BIAS>,
                             cudaFuncAttributeMaxDynamicSharedMemorySize, GEMM_SMEM);
        cudaFuncSetAttribute(h16gemm_kernel<EPI_GELU>,
                             cudaFuncAttributeMaxDynamicSharedMemorySize, GEMM_SMEM);
        cudaFuncSetAttribute(h16gemm_kernel<EPI_RESGATE>,
                             cudaFuncAttributeMaxDynamicSharedMemorySize, GEMM_SMEM);
        cudaFuncSetAttribute(flash_attn_kernel,
                             cudaFuncAttributeMaxDynamicSharedMemorySize, FL_SMEM);
        attr_set = true;
    }

    // 0) all weight transposes (single launch)
    transpose_all_kernel<<<12288, 256>>>(qkv_w, qkvw, proj_w, projw, w1, w1t, w2, w2t);

    // 1) LN1 -> fp16
    ln_kernel<<<ROWS / 8, 256>>>(x, ln1_g, ln1_b, xn);
    // 2) qkv: Q,K -> fp16; V -> f32 raw
    h16gemm_kernel<EPI_BIAS><<<dim3(3 * BDIM / 128, ROWS / 128), 128, GEMM_SMEM>>>(
        xn, qkvw, qkv_b, nullptr, nullptr, qkv, qkvh, ROWS, 3 * BDIM, BDIM);
    // 2b) V -> V^T fp16
    transpose_v_kernel<<<dim3(NSEQ / 32, HDIM / 32, NB * NHEADS), 256>>>(qkv, vt);
    // 3) fused attention -> ctx (fp16)
    flash_attn_kernel<<<dim3(NSEQ / 128, NB * NHEADS), 256, FL_SMEM>>>(qkvh, vt, mask, rel, ctx);
    // 4) y = x + gate1 * (ctx @ proj_w + proj_b)
    h16gemm_kernel<EPI_RESGATE><<<dim3(BDIM / 128, ROWS / 128), 128, GEMM_SMEM>>>(
        ctx, projw, proj_b, x, gate1, y, nullptr, ROWS, BDIM, BDIM);
    // 5) LN2 -> fp16
    ln_kernel<<<ROWS / 8, 256>>>(y, ln2_g, ln2_b, xn);
    // 6) mlp = gelu(xn @ w1 + b1) -> fp16
    h16gemm_kernel<EPI_GELU><<<dim3(4 * BDIM / 128, ROWS / 128), 128, GEMM_SMEM>>>(
        xn, w1t, b1, nullptr, nullptr, mlp, nullptr, ROWS, 4 * BDIM, BDIM);
    // 7) out = y + gate2 * (mlp @ w2 + b2)
    h16gemm_kernel<EPI_RESGATE><<<dim3(BDIM / 128, ROWS / 128), 128, GEMM_SMEM>>>(
        mlp, w2t, b2, y, gate2, out, nullptr, ROWS, BDIM, 4 * BDIM);
}

// round 16
// speedup vs baseline: 1.1826x; 1.1826x over previous
#include <cuda_runtime.h>
#include <cuda_fp16.h>
#include <math.h>
#include <stdint.h>

#define BDIM 1024
#define NB 4
#define NSEQ 1024
#define NHEADS 16
#define HDIM 64
#define ROWS (NB*NSEQ)   // 4096
#define MAXSEQ 1024

// ---------------- scratch (device globals; no allocation allowed) ----------------
__device__ __half g_xn[(size_t)ROWS*BDIM];              // fp16 LN out
__device__ float  g_qkv[(size_t)ROWS*3*BDIM];           // V third used (f32 raw)
__device__ __half g_qkvh[(size_t)ROWS*2*BDIM];          // Q,K fp16
__device__ __half g_vt[(size_t)ROWS*BDIM];              // V^T fp16: [bh*64+d][j]
__device__ __half g_ctx[(size_t)ROWS*BDIM];             // fp16
__device__ float  g_y[(size_t)ROWS*BDIM];
__device__ __half g_mlp[(size_t)ROWS*4*BDIM];
// fp16 TRANSPOSED weights [N, K] K-major
__device__ __half g_qkvw[(size_t)BDIM*3*BDIM];
__device__ __half g_projw[(size_t)BDIM*BDIM];
__device__ __half g_w1[(size_t)BDIM*4*BDIM];
__device__ __half g_w2[(size_t)4*BDIM*BDIM];

// ---------------- helpers ----------------
__device__ __forceinline__ void mma_f16(float c[4], const uint32_t a[4], const uint32_t b[2]) {
    asm volatile(
        "mma.sync.aligned.m16n8k16.row.col.f32.f16.f16.f32 "
        "{%0,%1,%2,%3}, {%4,%5,%6,%7}, {%8,%9}, {%0,%1,%2,%3};"
        : "+f"(c[0]), "+f"(c[1]), "+f"(c[2]), "+f"(c[3])
        : "r"(a[0]), "r"(a[1]), "r"(a[2]), "r"(a[3]), "r"(b[0]), "r"(b[1]));
}

__device__ __forceinline__ void ldsm_x4(uint32_t& r0, uint32_t& r1, uint32_t& r2, uint32_t& r3,
                                        uint32_t addr) {
    asm volatile("ldmatrix.sync.aligned.m8n8.x4.shared.b16 {%0,%1,%2,%3}, [%4];"
                 : "=r"(r0), "=r"(r1), "=r"(r2), "=r"(r3) : "r"(addr));
}

__device__ __forceinline__ void cp_async16(uint32_t smem_addr, const void* gptr) {
    asm volatile("cp.async.cg.shared.global [%0], [%1], 16;"
                 :: "r"(smem_addr), "l"(gptr));
}
__device__ __forceinline__ void cp_commit() { asm volatile("cp.async.commit_group;"); }
template<int N>
__device__ __forceinline__ void cp_wait() { asm volatile("cp.async.wait_group %0;" :: "n"(N)); }

__device__ __forceinline__ uint32_t h2u(__half2 h) { return *reinterpret_cast<uint32_t*>(&h); }

// ---------------- merged weight transpose + fp16 round (single launch) ----------------
__global__ __launch_bounds__(256) void transpose_all_kernel(
    const float* __restrict__ qkv_w, __half* __restrict__ qkvw,
    const float* __restrict__ proj_w, __half* __restrict__ projw,
    const float* __restrict__ w1, __half* __restrict__ w1t,
    const float* __restrict__ w2, __half* __restrict__ w2t)
{
    __shared__ float t[32][33];
    const int bid = blockIdx.x;
    const float* in; __half* out; int K, N, bx, by;
    if (bid < 3072)      { in = qkv_w;  out = qkvw;  K = 1024; N = 3072; bx = bid % 96;  by = bid / 96; }
    else if (bid < 4096) { int q = bid - 3072; in = proj_w; out = projw; K = 1024; N = 1024; bx = q % 32;  by = q / 32; }
    else if (bid < 8192) { int q = bid - 4096; in = w1;     out = w1t;   K = 1024; N = 4096; bx = q % 128; by = q / 128; }
    else                 { int q = bid - 8192; in = w2;     out = w2t;   K = 4096; N = 1024; bx = q % 32;  by = q / 32; }
    const int n0 = bx * 32, k0 = by * 32;
    const int tx = threadIdx.x & 31, ty = threadIdx.x >> 5;
    #pragma unroll
    for (int i = 0; i < 32; i += 8)
        t[ty + i][tx] = in[(size_t)(k0 + ty + i) * N + n0 + tx];
    __syncthreads();
    #pragma unroll
    for (int i = 0; i < 32; i += 8)
        out[(size_t)(n0 + ty + i) * K + k0 + tx] = __float2half_rn(t[tx][ty + i]);
}

// ---------------- V transpose: f32 [token][2048+h*64+d] -> fp16 [bh*64+d][j] ----------------
__global__ __launch_bounds__(256) void transpose_v_kernel(
    const float* __restrict__ qkvf, __half* __restrict__ vt)
{
    __shared__ float t[32][33];
    const int bh = blockIdx.z;
    const int b = bh >> 4, h = bh & 15;
    const int j0 = blockIdx.x * 32, d0 = blockIdx.y * 32;
    const int tx = threadIdx.x & 31, ty = threadIdx.x >> 5;
    #pragma unroll
    for (int i = 0; i < 32; i += 8)
        t[ty + i][tx] = qkvf[(size_t)(b * NSEQ + j0 + ty + i) * (3 * BDIM) + 2 * BDIM + h * HDIM + d0 + tx];
    __syncthreads();
    #pragma unroll
    for (int i = 0; i < 32; i += 8)
        vt[(size_t)(bh * HDIM + d0 + ty + i) * NSEQ + j0 + tx] = __float2half_rn(t[tx][ty + i]);
}

// ---------------- LayerNorm: warp per row; fp16 output ----------------
__global__ __launch_bounds__(256) void ln_kernel(const float* __restrict__ x,
    const float* __restrict__ g, const float* __restrict__ b, __half* __restrict__ out)
{
    const int row  = blockIdx.x * 8 + (threadIdx.x >> 5);
    const int lane = threadIdx.x & 31;
    const float4* xr = reinterpret_cast<const float4*>(x + (size_t)row * BDIM);
    float4 v[8];
    float s = 0.0f;
    #pragma unroll
    for (int i = 0; i < 8; i++) {
        v[i] = xr[lane + 32 * i];
        s += v[i].x + v[i].y + v[i].z + v[i].w;
    }
    #pragma unroll
    for (int o = 16; o > 0; o >>= 1) s += __shfl_xor_sync(0xffffffffu, s, o);
    const float mu = s * (1.0f / BDIM);
    float q = 0.0f;
    #pragma unroll
    for (int i = 0; i < 8; i++) {
        v[i].x -= mu; v[i].y -= mu; v[i].z -= mu; v[i].w -= mu;
        q += v[i].x*v[i].x + v[i].y*v[i].y + v[i].z*v[i].z + v[i].w*v[i].w;
    }
    #pragma unroll
    for (int o = 16; o > 0; o >>= 1) q += __shfl_xor_sync(0xffffffffu, q, o);
    const float rinv = rsqrtf(q * (1.0f / BDIM) + 1e-5f);
    __half* orow = out + (size_t)row * BDIM;
    #pragma unroll
    for (int i = 0; i < 8; i++) {
        float4 gg = reinterpret_cast<const float4*>(g)[lane + 32 * i];
        float4 bb = reinterpret_cast<const float4*>(b)[lane + 32 * i];
        __half2 h01 = __floats2half2_rn(v[i].x * rinv * gg.x + bb.x,
                                        v[i].y * rinv * gg.y + bb.y);
        __half2 h23 = __floats2half2_rn(v[i].z * rinv * gg.z + bb.z,
                                        v[i].w * rinv * gg.w + bb.w);
        uint2 u = { h2u(h01), h2u(h23) };
        *reinterpret_cast<uint2*>(orow + (lane + 32 * i) * 4) = u;
    }
}

// ---------------- 3-stage cp.async FP16 GEMM (R14 proven): XOR swizzle, 98KB, 2 CTA/SM ----------------
enum { EPI_BIAS = 0, EPI_GELU = 1, EPI_RESGATE = 2 };

#define FSTAGES 3
#define FSTAGE_B 32768
#define GEMM_SMEM (FSTAGES*FSTAGE_B)   // 98304 bytes

template<int EPI>
__global__ __launch_bounds__(128) void h16gemm_kernel(
    const __half* __restrict__ A, const __half* __restrict__ Wt,
    const float* __restrict__ bias, const float* __restrict__ res,
    const float* __restrict__ gate, void* __restrict__ Cv, void* __restrict__ Cv2,
    int M, int N, int K)
{
    constexpr int BK = 64;
    extern __shared__ uint32_t sm[];
    const uint32_t sm_u = (uint32_t)__cvta_generic_to_shared(sm);

    const int tid  = threadIdx.x;
    const int lane = tid & 31;
    const int wid  = tid >> 5;
    const int g    = lane >> 2;
    const int t4   = lane & 3;
    const int mWarp = (wid >> 1) * 64;
    const int nWarp = (wid & 1) * 64;

    const int lrow   = tid >> 3;
    const int lchunk = tid & 7;
    const uint32_t swb = (uint32_t)((lchunk * 16) ^ ((lrow & 3) << 5));

    const __half* Ap = A  + (size_t)(blockIdx.y * 128 + lrow) * K + lchunk * 8;
    const __half* Bp = Wt + (size_t)(blockIdx.x * 128 + lrow) * K + lchunk * 8;

    const int nT = K / BK;

    #pragma unroll
    for (int t = 0; t < FSTAGES - 1; t++) {
        const uint32_t ab = sm_u + t * FSTAGE_B;
        #pragma unroll
        for (int p = 0; p < 8; p++) {
            cp_async16(ab + (uint32_t)((lrow + p * 16) * 128) + swb,
                       Ap + (size_t)t * BK + (size_t)(p * 16) * K);
            cp_async16(ab + 16384u + (uint32_t)((lrow + p * 16) * 128) + swb,
                       Bp + (size_t)t * BK + (size_t)(p * 16) * K);
        }
        cp_commit();
    }

    float acc[4][8][4] = {};

    for (int t = 0; t < nT; t++) {
        cp_wait<FSTAGES - 2>();
        __syncthreads();

        const int tn = t + FSTAGES - 1;
        if (tn < nT) {
            int sl = tn % FSTAGES;
            const uint32_t ab = sm_u + sl * FSTAGE_B;
            #pragma unroll
            for (int p = 0; p < 8; p++) {
                cp_async16(ab + (uint32_t)((lrow + p * 16) * 128) + swb,
                           Ap + (size_t)tn * BK + (size_t)(p * 16) * K);
                cp_async16(ab + 16384u + (uint32_t)((lrow + p * 16) * 128) + swb,
                           Bp + (size_t)tn * BK + (size_t)(p * 16) * K);
            }
        }
        cp_commit();

        const uint32_t aB = sm_u + (t % FSTAGES) * FSTAGE_B;
        const uint32_t bB = aB + 16384u;
        const uint32_t gsw = (uint32_t)((g & 3) << 5);
        #pragma unroll
        for (int kc = 0; kc < 4; kc++) {
            const uint32_t koff = (uint32_t)((kc * 32 + 8 * t4)) ^ gsw;
            uint32_t bf[8][2];
            #pragma unroll
            for (int ni = 0; ni < 8; ni++) {
                uint2 bb;
                asm volatile("ld.shared.v2.b32 {%0,%1}, [%2];"
                             : "=r"(bb.x), "=r"(bb.y)
                             : "r"(bB + (uint32_t)((nWarp + ni * 8 + g) * 128) + koff));
                bf[ni][0] = bb.x; bf[ni][1] = bb.y;
            }
            #pragma unroll
            for (int mi = 0; mi < 4; mi++) {
                const int mb = mWarp + mi * 16;
                uint2 a0, a1;
                asm volatile("ld.shared.v2.b32 {%0,%1}, [%2];"
                             : "=r"(a0.x), "=r"(a0.y)
                             : "r"(aB + (uint32_t)((mb + g) * 128) + koff));
                asm volatile("ld.shared.v2.b32 {%0,%1}, [%2];"
                             : "=r"(a1.x), "=r"(a1.y)
                             : "r"(aB + (uint32_t)((mb + g + 8) * 128) + koff));
                uint32_t af[4] = { a0.x, a1.x, a0.y, a1.y };
                #pragma unroll
                for (int ni = 0; ni < 8; ni++)
                    mma_f16(acc[mi][ni], af, bf[ni]);
            }
        }
    }

    // epilogue
    const float gt = (EPI == EPI_RESGATE) ? gate[0] : 0.0f;
    #pragma unroll
    for (int mi = 0; mi < 4; mi++) {
        const int row0 = blockIdx.y * 128 + mWarp + mi * 16 + g;
        #pragma unroll
        for (int ni = 0; ni < 8; ni++) {
            const int col = blockIdx.x * 128 + nWarp + ni * 8 + t4 * 2;
            const float b0 = bias[col], b1 = bias[col + 1];
            #pragma unroll
            for (int h = 0; h < 2; h++) {
                const int row = row0 + h * 8;
                float v0 = acc[mi][ni][2 * h + 0] + b0;
                float v1 = acc[mi][ni][2 * h + 1] + b1;
                if (EPI == EPI_BIAS) {
                    if (col < 2 * BDIM) {
                        *reinterpret_cast<uint32_t*>((__half*)Cv2 + (size_t)row * (2 * BDIM) + col) =
                            h2u(__floats2half2_rn(v0, v1));
                    } else {
                        float* C = (float*)Cv;
                        *reinterpret_cast<float2*>(C + (size_t)row * N + col) = make_float2(v0, v1);
                    }
                }
                if (EPI == EPI_GELU) {
                    v0 = 0.5f * v0 * (1.0f + erff(v0 * 0.70710678118654752f));
                    v1 = 0.5f * v1 * (1.0f + erff(v1 * 0.70710678118654752f));
                    *reinterpret_cast<uint32_t*>((__half*)Cv + (size_t)row * N + col) =
                        h2u(__floats2half2_rn(v0, v1));
                }
                if (EPI == EPI_RESGATE) {
                    float* C = (float*)Cv;
                    const size_t off = (size_t)row * N + col;
                    *reinterpret_cast<float2*>(C + off) =
                        make_float2(res[off] + gt * v0, res[off + 1] + gt * v1);
                }
            }
        }
    }
}

// ---------------- Fused flash attention: fp16 + ldmatrix, padded 144B strides (R15 flash) ----------------
#define FROWB 144
#define K_BYTES (64*FROWB)             // 9216
#define VT_BYTES (64*FROWB)            // 9216
#define SLOT_B  (K_BYTES+VT_BYTES)     // 18432
#define MK_B    (2*SLOT_B)             // 36864
#define REL_B   (MK_B + 512)           // 37376
#define FL_SMEM (REL_B + 8192)         // 45568 bytes

__global__ __launch_bounds__(256, 2) void flash_attn_kernel(
    const __half* __restrict__ qkvh, const __half* __restrict__ vt,
    const int* __restrict__ mask, const float* __restrict__ rel,
    __half* __restrict__ ctx)
{
    constexpr float SCALE = 0.125f;
    constexpr float L2E = 1.4426950408889634f;

    extern __shared__ __align__(16) char smc[];
    const uint32_t sm_u = (uint32_t)__cvta_generic_to_shared(smc);
    const int* mki  = reinterpret_cast<const int*>(smc + MK_B);
    float* rel_s    = reinterpret_cast<float*>(smc + REL_B);

    const int bh = blockIdx.y;
    const int b = bh >> 4, h = bh & 15;
    const int i0 = blockIdx.x * 128;
    const int tid = threadIdx.x, lane = tid & 31, w = tid >> 5;
    const int g = lane >> 2, t4 = lane & 3;

    const int lq = lane >> 3, lr8 = lane & 7;
    const uint32_t laneoff = (uint32_t)(((lq & 1) * 8 + lr8) * FROWB + (lq >> 1) * 16);

    // loaders: K rows (tokens) / Vt rows (d)
    const int ldr = tid >> 2;
    const int kc  = tid & 3;
    const __half* khbase = qkvh + (size_t)(b * NSEQ + ldr) * (2 * BDIM) + BDIM + h * HDIM + kc * 16;
    const __half* vtbase = vt + (size_t)(bh * HDIM + ldr) * NSEQ + kc * 16;

    // prologue: tile 0 -> slot 0
    {
        const uint32_t kdst = sm_u + (uint32_t)(ldr * FROWB + kc * 32);
        cp_async16(kdst, khbase);
        cp_async16(kdst + 16, khbase + 8);
        const uint32_t vdst = sm_u + (uint32_t)(K_BYTES + ldr * FROWB + kc * 32);
        cp_async16(vdst, vtbase);
        cp_async16(vdst + 16, vtbase + 8);
        if (tid < 16)
            cp_async16(sm_u + (uint32_t)(MK_B + tid * 16), mask + b * NSEQ + tid * 4);
        cp_commit();
    }

    for (int idx = tid; idx < 2 * MAXSEQ - 1; idx += 256)
        rel_s[idx] = rel[(size_t)idx * NHEADS + h];

    const int irow0 = i0 + w * 16 + g;
    const int irow1 = irow0 + 8;

    // Q a-fragments from gmem, STANDARD layout
    uint32_t Qa[4][4];
    {
        const char* q0b = (const char*)(qkvh + (size_t)(b * NSEQ + irow0) * (2 * BDIM) + h * HDIM);
        const char* q1b = (const char*)(qkvh + (size_t)(b * NSEQ + irow1) * (2 * BDIM) + h * HDIM);
        #pragma unroll
        for (int kt = 0; kt < 4; kt++) {
            Qa[kt][0] = *reinterpret_cast<const uint32_t*>(q0b + kt * 32 + 4 * t4);
            Qa[kt][1] = *reinterpret_cast<const uint32_t*>(q1b + kt * 32 + 4 * t4);
            Qa[kt][2] = *reinterpret_cast<const uint32_t*>(q0b + kt * 32 + 16 + 4 * t4);
            Qa[kt][3] = *reinterpret_cast<const uint32_t*>(q1b + kt * 32 + 16 + 4 * t4);
        }
    }

    const int mi0 = mask[b * NSEQ + irow0];
    const int mi1 = mask[b * NSEQ + irow1];

    float m0 = -INFINITY, m1 = -INFINITY, l0 = 0.0f, l1 = 0.0f;
    float Oc[8][4] = {};

    for (int jt = 0; jt < NSEQ / 64; jt++) {
        cp_wait<0>();
        __syncthreads();

        if (jt + 1 < NSEQ / 64) {
            const int ns = (jt + 1) & 1;
            const __half* kp = khbase + (size_t)(jt + 1) * 64 * (2 * BDIM);
            const __half* vp = vtbase + (size_t)(jt + 1) * 64;
            const uint32_t kdst = sm_u + (uint32_t)(ns * SLOT_B + ldr * FROWB + kc * 32);
            cp_async16(kdst, kp);
            cp_async16(kdst + 16, kp + 8);
            const uint32_t vdst = sm_u + (uint32_t)(ns * SLOT_B + K_BYTES + ldr * FROWB + kc * 32);
            cp_async16(vdst, vp);
            cp_async16(vdst + 16, vp + 8);
            if (tid < 16)
                cp_async16(sm_u + (uint32_t)(MK_B + ns * 256 + tid * 16),
                           mask + b * NSEQ + (jt + 1) * 64 + tid * 4);
            cp_commit();
        }

        const int slot = jt & 1;
        const uint32_t kR = sm_u + (uint32_t)(slot * SLOT_B) + laneoff;
        const uint32_t vR = kR + K_BYTES;
        const int* mkp = mki + slot * 64;

        // S = Q @ K^T  (fp16; K b-frags via ldmatrix)
        float S[8][4] = {};
        #pragma unroll
        for (int kt = 0; kt < 4; kt++) {
            uint32_t kb[8][2];
            #pragma unroll
            for (int ntp = 0; ntp < 4; ntp++) {
                uint32_t r0, r1, r2, r3;
                ldsm_x4(r0, r1, r2, r3, kR + (uint32_t)(ntp * 16 * FROWB + kt * 32));
                kb[2*ntp][0] = r0; kb[2*ntp][1] = r2;
                kb[2*ntp+1][0] = r1; kb[2*ntp+1][1] = r3;
            }
            #pragma unroll
            for (int nt = 0; nt < 8; nt++)
                mma_f16(S[nt], Qa[kt], kb[nt]);
        }

        // scale + rel bias + mask; row max
        float tmax0 = -INFINITY, tmax1 = -INFINITY;
        #pragma unroll
        for (int nt = 0; nt < 8; nt++) {
            const int j0 = jt * 64 + nt * 8 + 2 * t4;
            const int mk0 = mkp[nt * 8 + 2 * t4];
            const int mk1 = mkp[nt * 8 + 2 * t4 + 1];
            float s0 = S[nt][0] * SCALE + rel_s[irow0 - j0 + (MAXSEQ - 1)];
            float s1 = S[nt][1] * SCALE + rel_s[irow0 - j0 - 1 + (MAXSEQ - 1)];
            float s2 = S[nt][2] * SCALE + rel_s[irow1 - j0 + (MAXSEQ - 1)];
            float s3 = S[nt][3] * SCALE + rel_s[irow1 - j0 - 1 + (MAXSEQ - 1)];
            if (mi0 == 0 || mk0 == 0) s0 = -1e9f;
            if (mi0 == 0 || mk1 == 0) s1 = -1e9f;
            if (mi1 == 0 || mk0 == 0) s2 = -1e9f;
            if (mi1 == 0 || mk1 == 0) s3 = -1e9f;
            S[nt][0] = s0; S[nt][1] = s1; S[nt][2] = s2; S[nt][3] = s3;
            tmax0 = fmaxf(tmax0, fmaxf(s0, s1));
            tmax1 = fmaxf(tmax1, fmaxf(s2, s3));
        }
        tmax0 = fmaxf(tmax0, __shfl_xor_sync(0xffffffffu, tmax0, 1));
        tmax0 = fmaxf(tmax0, __shfl_xor_sync(0xffffffffu, tmax0, 2));
        tmax1 = fmaxf(tmax1, __shfl_xor_sync(0xffffffffu, tmax1, 1));
        tmax1 = fmaxf(tmax1, __shfl_xor_sync(0xffffffffu, tmax1, 2));

        const float mn0 = fmaxf(m0, tmax0);
        const float mn1 = fmaxf(m1, tmax1);
        const float sc0 = exp2f((m0 - mn0) * L2E);
        const float sc1 = exp2f((m1 - mn1) * L2E);
        m0 = mn0; m1 = mn1;

        float ts0 = 0.0f, ts1 = 0.0f;
        #pragma unroll
        for (int nt = 0; nt < 8; nt++) {
            S[nt][0] = exp2f((S[nt][0] - mn0) * L2E);
            S[nt][1] = exp2f((S[nt][1] - mn0) * L2E);
            S[nt][2] = exp2f((S[nt][2] - mn1) * L2E);
            S[nt][3] = exp2f((S[nt][3] - mn1) * L2E);
            ts0 += S[nt][0] + S[nt][1];
            ts1 += S[nt][2] + S[nt][3];
        }
        ts0 += __shfl_xor_sync(0xffffffffu, ts0, 1);
        ts0 += __shfl_xor_sync(0xffffffffu, ts0, 2);
        ts1 += __shfl_xor_sync(0xffffffffu, ts1, 1);
        ts1 += __shfl_xor_sync(0xffffffffu, ts1, 2);
        l0 = l0 * sc0 + ts0;
        l1 = l1 * sc1 + ts1;

        #pragma unroll
        for (int nt = 0; nt < 8; nt++) {
            Oc[nt][0] *= sc0; Oc[nt][1] *= sc0;
            Oc[nt][2] *= sc1; Oc[nt][3] *= sc1;
        }

        // O += P @ V : a-frag = packed S regs (standard), b-frag = V^T via ldmatrix
        #pragma unroll
        for (int kcc = 0; kcc < 4; kcc++) {
            const int nt0 = 2 * kcc, nt1 = nt0 + 1;
            uint32_t af[4];
            af[0] = h2u(__floats2half2_rn(S[nt0][0], S[nt0][1]));
            af[1] = h2u(__floats2half2_rn(S[nt0][2], S[nt0][3]));
            af[2] = h2u(__floats2half2_rn(S[nt1][0], S[nt1][1]));
            af[3] = h2u(__floats2half2_rn(S[nt1][2], S[nt1][3]));
            uint32_t vb[8][2];
            #pragma unroll
            for (int ntp = 0; ntp < 4; ntp++) {
                uint32_t r0, r1, r2, r3;
                ldsm_x4(r0, r1, r2, r3, vR + (uint32_t)(ntp * 16 * FROWB + kcc * 32));
                vb[2*ntp][0] = r0; vb[2*ntp][1] = r2;
                vb[2*ntp+1][0] = r1; vb[2*ntp+1][1] = r3;
            }
            #pragma unroll
            for (int nt = 0; nt < 8; nt++)
                mma_f16(Oc[nt], af, vb[nt]);
        }
    }

    // writeback ctx = O / l -> fp16
    const float inv0 = 1.0f / l0;
    const float inv1 = 1.0f / l1;
    #pragma unroll
    for (int nt = 0; nt < 8; nt++) {
        const int col = h * HDIM + nt * 8 + 2 * t4;
        *reinterpret_cast<uint32_t*>(ctx + (size_t)(b * NSEQ + irow0) * BDIM + col) =
            h2u(__floats2half2_rn(Oc[nt][0] * inv0, Oc[nt][1] * inv0));
        *reinterpret_cast<uint32_t*>(ctx + (size_t)(b * NSEQ + irow1) * BDIM + col) =
            h2u(__floats2half2_rn(Oc[nt][2] * inv1, Oc[nt][3] * inv1));
    }
}

// ---------------- launch ----------------
extern "C" void kernel_launch(void* const* d_in, const int* in_sizes, int n_in,
                              void* d_out, int out_size)
{
    const float* x      = (const float*)d_in[0];
    const int*   mask   = (const int*)  d_in[1];
    const float* ln1_g  = (const float*)d_in[2];
    const float* ln1_b  = (const float*)d_in[3];
    const float* qkv_w  = (const float*)d_in[4];
    const float* qkv_b  = (const float*)d_in[5];
    const float* proj_w = (const float*)d_in[6];
    const float* proj_b = (const float*)d_in[7];
    const float* rel    = (const float*)d_in[8];
    const float* ln2_g  = (const float*)d_in[9];
    const float* ln2_b  = (const float*)d_in[10];
    const float* w1     = (const float*)d_in[11];
    const float* b1     = (const float*)d_in[12];
    const float* w2     = (const float*)d_in[13];
    const float* b2     = (const float*)d_in[14];
    const float* gate1  = (const float*)d_in[15];
    const float* gate2  = (const float*)d_in[16];
    float* out = (float*)d_out;

    __half *xn, *ctx, *mlp, *qkvw, *projw, *w1t, *w2t, *qkvh, *vt;
    float *qkv, *y;
    cudaGetSymbolAddress((void**)&xn,    g_xn);
    cudaGetSymbolAddress((void**)&qkv,   g_qkv);
    cudaGetSymbolAddress((void**)&qkvh,  g_qkvh);
    cudaGetSymbolAddress((void**)&vt,    g_vt);
    cudaGetSymbolAddress((void**)&ctx,   g_ctx);
    cudaGetSymbolAddress((void**)&y,     g_y);
    cudaGetSymbolAddress((void**)&mlp,   g_mlp);
    cudaGetSymbolAddress((void**)&qkvw,  g_qkvw);
    cudaGetSymbolAddress((void**)&projw, g_projw);
    cudaGetSymbolAddress((void**)&w1t,   g_w1);
    cudaGetSymbolAddress((void**)&w2t,   g_w2);

    static bool attr_set = false;
    if (!attr_set) {
        cudaFuncSetAttribute(h16gemm_kernel<EPI_BIAS>,
                             cudaFuncAttributeMaxDynamicSharedMemorySize, GEMM_SMEM);
        cudaFuncSetAttribute(h16gemm_kernel<EPI_GELU>,
                             cudaFuncAttributeMaxDynamicSharedMemorySize, GEMM_SMEM);
        cudaFuncSetAttribute(h16gemm_kernel<EPI_RESGATE>,
                             cudaFuncAttributeMaxDynamicSharedMemorySize, GEMM_SMEM);
        cudaFuncSetAttribute(flash_attn_kernel,
                             cudaFuncAttributeMaxDynamicSharedMemorySize, FL_SMEM);
        attr_set = true;
    }

    // 0) all weight transposes (single launch)
    transpose_all_kernel<<<12288, 256>>>(qkv_w, qkvw, proj_w, projw, w1, w1t, w2, w2t);

    // 1) LN1 -> fp16
    ln_kernel<<<ROWS / 8, 256>>>(x, ln1_g, ln1_b, xn);
    // 2) qkv: Q,K -> fp16; V -> f32 raw
    h16gemm_kernel<EPI_BIAS><<<dim3(3 * BDIM / 128, ROWS / 128), 128, GEMM_SMEM>>>(
        xn, qkvw, qkv_b, nullptr, nullptr, qkv, qkvh, ROWS, 3 * BDIM, BDIM);
    // 2b) V -> V^T fp16
    transpose_v_kernel<<<dim3(NSEQ / 32, HDIM / 32, NB * NHEADS), 256>>>(qkv, vt);
    // 3) fused attention -> ctx (fp16)
    flash_attn_kernel<<<dim3(NSEQ / 128, NB * NHEADS), 256, FL_SMEM>>>(qkvh, vt, mask, rel, ctx);
    // 4) y = x + gate1 * (ctx @ proj_w + proj_b)
    h16gemm_kernel<EPI_RESGATE><<<dim3(BDIM / 128, ROWS / 128), 128, GEMM_SMEM>>>(
        ctx, projw, proj_b, x, gate1, y, nullptr, ROWS, BDIM, BDIM);
    // 5) LN2 -> fp16
    ln_kernel<<<ROWS / 8, 256>>>(y, ln2_g, ln2_b, xn);
    // 6) mlp = gelu(xn @ w1 + b1) -> fp16
    h16gemm_kernel<EPI_GELU><<<dim3(4 * BDIM / 128, ROWS / 128), 128, GEMM_SMEM>>>(
        xn, w1t, b1, nullptr, nullptr, mlp, nullptr, ROWS, 4 * BDIM, BDIM);
    // 7) out = y + gate2 * (mlp @ w2 + b2)
    h16gemm_kernel<EPI_RESGATE><<<dim3(BDIM / 128, ROWS / 128), 128, GEMM_SMEM>>>(
        mlp, w2t, b2, y, gate2, out, nullptr, ROWS, BDIM, 4 * BDIM);
}